// round 14
// baseline (speedup 1.0000x reference)
#include <cuda_runtime.h>
#include <math.h>

#define HW     16384
#define NCH    512
#define NC     16       // classes per group (C)
#define NG     32       // groups (G)
#define NB     8        // batch
#define NPAIR  120      // C*(C-1)/2
#define NBG    256      // NB*NG
#define TILE   256      // floats per channel per pipeline tile (1 KB)
#define NT     (HW / TILE)      // 64 tiles: one CTA covers the FULL HW
#define STAGES 6
#define DEPTH  4                // tiles in flight (64 KB per CTA)
#define STAGE_FLOATS (NC * TILE)                   // 4096 floats = 16 KB
#define STAGE_BYTES  (STAGE_FLOATS * 4)
#define MBAR_OFF     (STAGES * STAGE_BYTES)        // mbarriers after stages
#define SMEM_BYTES   (MBAR_OFF + 128)              // + full[6] free[6] pads

// Device-global scratch (no allocations allowed)
__device__ int   g_chan[NG][NC];        // channel id: rank-g pick of class c
__device__ float g_wgt[NG][NC];         // sigmoid(|w|) of that pick

// ---------------------------------------------------------------------------
// mbarrier helpers
// ---------------------------------------------------------------------------
#define MBAR_INIT(addr, cnt) \
    asm volatile("mbarrier.init.shared::cta.b64 [%0], %1;" \
                 :: "r"(addr), "r"(cnt) : "memory")

#define MBAR_ARRIVE(addr) \
    asm volatile("mbarrier.arrive.shared::cta.b64 _, [%0];" \
                 :: "r"(addr) : "memory")

#define CPASYNC_MBAR_ARRIVE(addr) \
    asm volatile("cp.async.mbarrier.arrive.noinc.shared::cta.b64 [%0];" \
                 :: "r"(addr) : "memory")

#define MBAR_WAIT(addr, parity) do {                                         \
    asm volatile("{\n\t.reg .pred P1;\n\t"                                   \
        "WL_%=:\n\t"                                                         \
        "mbarrier.try_wait.parity.acquire.cta.shared::cta.b64 P1, [%0], %1, 0x989680;\n\t" \
        "@P1 bra.uni WD_%=;\n\t"                                             \
        "bra.uni WL_%=;\n\t"                                                 \
        "WD_%=:\n\t}" :: "r"(addr), "r"(parity) : "memory");                 \
} while (0)

// ---------------------------------------------------------------------------
// Kernel A: selection via rank counting (unchanged; measured 5.2-5.6us).
// Also zeroes out[0] (poisoned by harness; gram atomically accumulates).
// ---------------------------------------------------------------------------
__global__ void select_kernel(const float* __restrict__ cw,
                              float* __restrict__ out) {
    __shared__ float sw[NCH];
    const int j   = blockIdx.x;          // class
    const int q   = blockIdx.y;          // channel chunk (8 x 64)
    const int tid = threadIdx.x;

    if (j == 0 && q == 0 && tid == 0) out[0] = 0.0f;

    sw[tid] = fabsf(cw[j * NCH + tid]);
    __syncthreads();

    const int chl = tid >> 3;            // 0..63 channel-in-chunk
    const int sl  = tid & 7;             // compare slice
    const int i   = q * 64 + chl;        // global channel
    const float wi = sw[i];

    int r = 0;
    #pragma unroll 8
    for (int m = 0; m < 64; m++) {
        const int k = sl + (m << 3);     // interleaved: conflict-free
        const float wk = sw[k];
        r += (wk > wi) || (wk == wi && k < i);
    }
    r += __shfl_xor_sync(0xffffffffu, r, 1);
    r += __shfl_xor_sync(0xffffffffu, r, 2);
    r += __shfl_xor_sync(0xffffffffu, r, 4);

    if (sl == 0 && r < NG) {
        g_chan[r][j] = i;
        g_wgt[r][j]  = 1.0f / (1.0f + expf(-wi));
    }
}

// ---------------------------------------------------------------------------
// Kernel B: Gram + fused finalize, DECOUPLED mbarrier pipeline.
// One CTA per (b,g), grid=256 (single wave), NT=64, STAGES=6, DEPTH=4.
// No per-tile __syncthreads: full[s] flips via cp.async.mbarrier.arrive.noinc
// (256 per-thread async arrives), free[s] flips via 256 post-consume arrives.
// Warps slip up to ~2 tiles relative to each other -> latency overlap.
//   loader role:  channel mc = tid>>4; 16 threads/channel, 64 B each.
//   compute role: grp = tid>>7 picks pair-half [0,60)/[60,120);
//                 lt2 = tid&127 is the float2 position in the tile.
// Scalar FFMA body (107 regs measured) + small cursor state.
// ---------------------------------------------------------------------------
template <int P0>
__device__ __forceinline__ void do_pairs60(const float2* __restrict__ v,
                                           float* __restrict__ acc) {
    int p = 0;
    #pragma unroll
    for (int c = 0; c < NC; c++) {
        #pragma unroll
        for (int d = c + 1; d < NC; d++) {
            if (p >= P0 && p < P0 + 60) {
                acc[p - P0] = fmaf(v[c].x, v[d].x,
                              fmaf(v[c].y, v[d].y, acc[p - P0]));
            }
            p++;
        }
    }
}

__global__ __launch_bounds__(256, 2) void gram_kernel(const float* __restrict__ x,
                                                      float* __restrict__ out) {
    extern __shared__ __align__(16) float s_buf[];   // [STAGES][NC][TILE] + mbars

    const int bg  = blockIdx.x;          // one CTA per (b,g)
    const int b   = bg >> 5;
    const int g   = bg & 31;
    const int tid = threadIdx.x;

    const unsigned smem_base = (unsigned)__cvta_generic_to_shared(s_buf);
    const unsigned mb_full   = smem_base + MBAR_OFF;        // full[s] = +8s
    const unsigned mb_free   = smem_base + MBAR_OFF + 48;   // free[s] = +8s

    if (tid == 0) {
        #pragma unroll
        for (int s = 0; s < STAGES; s++) {
            MBAR_INIT(mb_full + 8 * s, 256);
            MBAR_INIT(mb_free + 8 * s, 256);
        }
    }
    __syncthreads();                     // mbarriers visible before any use

    // loader role: 16 threads per channel
    const int mc = tid >> 4;             // channel 0..15
    const int ms = tid & 15;             // float4 slot within channel slice
    const float* src = x + ((size_t)(b * NCH + g_chan[g][mc])) * HW;

    // compute role
    const int grp  = tid >> 7;           // pair half: [0,60) or [60,120)
    const int lt2  = tid & 127;          // float2 position in tile
    const int warp = tid >> 5;
    const int lane = tid & 31;

    auto issue = [&](int t) {
        const int stage = t % STAGES;
        const float4* gp = reinterpret_cast<const float4*>(src + t * TILE) + ms;
        unsigned sa = smem_base + stage * STAGE_BYTES + (mc * TILE + ms * 4) * 4;
        #pragma unroll
        for (int k = 0; k < 4; k++) {
            asm volatile("cp.async.cg.shared.global [%0], [%1], 16;\n"
                         :: "r"(sa + 256 * k), "l"(gp + 16 * k) : "memory");
        }
        CPASYNC_MBAR_ARRIVE(mb_full + 8 * stage);   // fires when copies land
    };

    float acc[60];
    #pragma unroll
    for (int p = 0; p < 60; p++) acc[p] = 0.0f;

    // prologue: DEPTH tiles in flight (stages untouched yet, no free wait)
    #pragma unroll
    for (int t = 0; t < DEPTH; t++) issue(t);

    for (int t = 0; t < NT; t++) {
        const int s = t % STAGES;
        MBAR_WAIT(mb_full + 8 * s, (t / STAGES) & 1);   // tile t landed

        const float2* sm = reinterpret_cast<const float2*>(
                               &s_buf[s * STAGE_FLOATS]);
        float2 v[NC];
        #pragma unroll
        for (int c = 0; c < NC; c++) v[c] = sm[c * (TILE / 2) + lt2];

        if (grp == 0) do_pairs60<0 >(v, acc);
        else          do_pairs60<60>(v, acc);

        MBAR_ARRIVE(mb_free + 8 * s);                   // done with tile t

        const int tf = t + DEPTH;
        if (tf < NT) {
            const int sf = tf % STAGES;
            if (tf >= STAGES)
                MBAR_WAIT(mb_free + 8 * sf, (tf / STAGES - 1) & 1);
            issue(tf);
        }
    }

    __syncthreads();   // all warps done with all stages before smem reuse

    // cross-warp reduce: butterfly -> smem partials [8 warps][60]
    float* s_part = s_buf;
    #pragma unroll
    for (int p = 0; p < 60; p++) {
        float vv = acc[p];
        vv += __shfl_xor_sync(0xffffffffu, vv, 16);
        vv += __shfl_xor_sync(0xffffffffu, vv, 8);
        vv += __shfl_xor_sync(0xffffffffu, vv, 4);
        vv += __shfl_xor_sync(0xffffffffu, vv, 2);
        vv += __shfl_xor_sync(0xffffffffu, vv, 1);
        if (lane == 0) s_part[warp * 60 + p] = vv;
    }
    __syncthreads();

    // ---- fused finalize: weighted |S| for this bg, margin, clamp, atomic ----
    float* s_red = s_buf + 512;          // 4 floats, past the partials region
    float val = 0.0f;
    if (tid < NPAIR) {
        const int h  = tid / 60;         // which pair-half produced this pair
        const int pp = tid % 60;
        float S = 0.0f;
        #pragma unroll
        for (int w = 0; w < 4; w++) S += s_part[(h * 4 + w) * 60 + pp];

        // decode pair tid -> (c, d)
        int c = 0, rem = tid;
        #pragma unroll
        for (int cc = 0; cc < NC - 1; cc++) {
            const int row = NC - 1 - cc;      // pairs in row cc
            if (rem >= row && c == cc) { rem -= row; c = cc + 1; }
        }
        const int d = c + 1 + rem;

        val = g_wgt[g][c] * g_wgt[g][d] * fabsf(S);
    }

    val += __shfl_xor_sync(0xffffffffu, val, 16);
    val += __shfl_xor_sync(0xffffffffu, val, 8);
    val += __shfl_xor_sync(0xffffffffu, val, 4);
    val += __shfl_xor_sync(0xffffffffu, val, 2);
    val += __shfl_xor_sync(0xffffffffu, val, 1);
    if (lane == 0 && warp < 4) s_red[warp] = val;
    __syncthreads();

    if (tid == 0) {
        const float tot = s_red[0] + s_red[1] + s_red[2] + s_red[3];
        const float sum_abs_cov = tot / (float)(HW - 1);
        const float off_diag    = sum_abs_cov - 60.0f;   // margin = floor(120/2)
        const float loss        = fmaxf(off_diag / 120.0f, 0.0f);
        atomicAdd(out, loss / (float)NB);
    }
}

// ---------------------------------------------------------------------------
extern "C" void kernel_launch(void* const* d_in, const int* in_sizes, int n_in,
                              void* d_out, int out_size) {
    (void)in_sizes; (void)n_in; (void)out_size;
    const float* x  = (const float*)d_in[0];   // [8,512,128,128] fp32
    const float* cw = (const float*)d_in[1];   // [19,512] fp32

    cudaFuncSetAttribute(gram_kernel,
                         cudaFuncAttributeMaxDynamicSharedMemorySize,
                         SMEM_BYTES);

    select_kernel<<<dim3(16, 8), 512>>>(cw, (float*)d_out);
    gram_kernel<<<NBG, 256, SMEM_BYTES>>>(x, (float*)d_out);
}

// round 15
// speedup vs baseline: 1.0599x; 1.0599x over previous
#include <cuda_runtime.h>
#include <math.h>

#define HW     16384
#define NCH    512
#define NC     16       // classes per group (C)
#define NG     32       // groups (G)
#define NB     8        // batch
#define NPAIR  120      // C*(C-1)/2
#define NBG    256      // NB*NG
#define TILE   256      // floats per channel per pipeline tile (1 KB)
#define NT     (HW / TILE)      // 64 tiles: one CTA covers the FULL HW
#define STAGES 6
#define DEPTH  5                // tiles in flight (80 KB per CTA)
#define STAGE_FLOATS (NC * TILE)                   // 4096 floats = 16 KB
#define SMEM_BYTES   (STAGES * STAGE_FLOATS * 4)   // 96 KB dynamic per CTA

typedef unsigned long long ull;

// Device-global scratch (no allocations allowed)
__device__ int   g_chan[NG][NC];        // channel id: rank-g pick of class c
__device__ float g_wgt[NG][NC];         // sigmoid(|w|) of that pick

// ---------------------------------------------------------------------------
// Kernel A: selection via rank counting (unchanged; measured 5.2-5.6us).
// Also zeroes out[0] (poisoned by harness; gram atomically accumulates).
// ---------------------------------------------------------------------------
__global__ void select_kernel(const float* __restrict__ cw,
                              float* __restrict__ out) {
    __shared__ float sw[NCH];
    const int j   = blockIdx.x;          // class
    const int q   = blockIdx.y;          // channel chunk (8 x 64)
    const int tid = threadIdx.x;

    if (j == 0 && q == 0 && tid == 0) out[0] = 0.0f;

    sw[tid] = fabsf(cw[j * NCH + tid]);
    __syncthreads();

    const int chl = tid >> 3;            // 0..63 channel-in-chunk
    const int sl  = tid & 7;             // compare slice
    const int i   = q * 64 + chl;        // global channel
    const float wi = sw[i];

    int r = 0;
    #pragma unroll 8
    for (int m = 0; m < 64; m++) {
        const int k = sl + (m << 3);     // interleaved: conflict-free
        const float wk = sw[k];
        r += (wk > wi) || (wk == wi && k < i);
    }
    r += __shfl_xor_sync(0xffffffffu, r, 1);
    r += __shfl_xor_sync(0xffffffffu, r, 2);
    r += __shfl_xor_sync(0xffffffffu, r, 4);

    if (sl == 0 && r < NG) {
        g_chan[r][j] = i;
        g_wgt[r][j]  = 1.0f / (1.0f + expf(-wi));
    }
}

// ---------------------------------------------------------------------------
// Kernel B: Gram + fused finalize, FFMA2 compute, LDS.128 tile reads.
// One CTA per (b,g), grid=256 (single wave), NT=64, 6-stage depth-5 cp.async
// with per-tile wait_group+__syncthreads (measured-best sync structure; the
// mbarrier variant regressed).
// 256 threads = 4 pair-groups x 64 threads; thread lt covers ADJACENT ull
// positions 2lt, 2lt+1 -> one 16B shared load per channel (was 2x LDS.64).
//   G0 (w0-1): 28 pairs within ch 0-7
//   G1 (w2-3): 28 pairs within ch 8-15
//   G2 (w4-5): 32 pairs c in 0-7, d in 8-11
//   G3 (w6-7): 32 pairs c in 0-7, d in 12-15
// Both sample-pairs of a position-pair accumulate into the SAME packed
// f32x2 acc (register count unchanged vs R13).
// ---------------------------------------------------------------------------
__device__ __forceinline__ void fma2(ull& a, ull b, ull c) {
    asm("fma.rn.f32x2 %0, %1, %2, %0;" : "+l"(a) : "l"(b), "l"(c));
}

template <int B>
__device__ __forceinline__ void body_oct(const ulonglong2* __restrict__ smu2,
                                         int lt, ull* __restrict__ acc) {
    ulonglong2 v[8];
    #pragma unroll
    for (int j = 0; j < 8; j++) v[j] = smu2[(B + j) * 64 + lt];
    int s = 0;
    #pragma unroll
    for (int c = 0; c < 8; c++)
        #pragma unroll
        for (int d = c + 1; d < 8; d++) {
            fma2(acc[s], v[c].x, v[d].x);
            fma2(acc[s], v[c].y, v[d].y);
            s++;
        }
}

template <int HB>
__device__ __forceinline__ void body_cross(const ulonglong2* __restrict__ smu2,
                                           int lt, ull* __restrict__ acc) {
    ulonglong2 vh[4];
    #pragma unroll
    for (int k = 0; k < 4; k++) vh[k] = smu2[(HB + k) * 64 + lt];
    #pragma unroll
    for (int c = 0; c < 8; c++) {
        const ulonglong2 vc = smu2[c * 64 + lt];
        #pragma unroll
        for (int k = 0; k < 4; k++) {
            fma2(acc[c * 4 + k], vc.x, vh[k].x);
            fma2(acc[c * 4 + k], vc.y, vh[k].y);
        }
    }
}

__global__ __launch_bounds__(256, 2) void gram_kernel(const float* __restrict__ x,
                                                      float* __restrict__ out) {
    extern __shared__ __align__(16) float s_buf[];   // [STAGES][NC][TILE]

    const int bg  = blockIdx.x;          // one CTA per (b,g)
    const int b   = bg >> 5;
    const int g   = bg & 31;
    const int tid = threadIdx.x;

    // loader role: 16 threads per channel
    const int mc = tid >> 4;             // channel 0..15
    const int ms = tid & 15;             // float4 slot within channel slice
    const float* src = x + ((size_t)(b * NCH + g_chan[g][mc])) * HW;

    // compute role
    const int grp  = tid >> 6;           // pair group 0..3 (2 warps each)
    const int lt   = tid & 63;           // ull2 position (covers ull 2lt,2lt+1)
    const int warp = tid >> 5;
    const int lane = tid & 31;

    auto issue = [&](int t) {
        const int stage = t % STAGES;
        const float4* gp = reinterpret_cast<const float4*>(src + t * TILE) + ms;
        float4* sp = reinterpret_cast<float4*>(
                         &s_buf[stage * STAGE_FLOATS + mc * TILE]) + ms;
        #pragma unroll
        for (int k = 0; k < 4; k++) {
            unsigned sa = (unsigned)__cvta_generic_to_shared(sp + 16 * k);
            asm volatile("cp.async.cg.shared.global [%0], [%1], 16;\n"
                         :: "r"(sa), "l"(gp + 16 * k) : "memory");
        }
        asm volatile("cp.async.commit_group;" ::: "memory");
    };

    ull acc[32];
    #pragma unroll
    for (int p = 0; p < 32; p++) acc[p] = 0ull;

    // prologue: DEPTH tiles in flight (one refill for the whole bg)
    #pragma unroll
    for (int t = 0; t < DEPTH; t++) issue(t);

    for (int t = 0; t < NT; t++) {
        asm volatile("cp.async.wait_group %0;" :: "n"(DEPTH - 1) : "memory");
        __syncthreads();                 // tile t visible; stage (t-1)%6 free

        const ulonglong2* smu2 = reinterpret_cast<const ulonglong2*>(
                                     &s_buf[(t % STAGES) * STAGE_FLOATS]);

        if      (grp == 0) body_oct<0>  (smu2, lt, acc);
        else if (grp == 1) body_oct<8>  (smu2, lt, acc);
        else if (grp == 2) body_cross<8> (smu2, lt, acc);
        else               body_cross<12>(smu2, lt, acc);

        if (t + DEPTH < NT) issue(t + DEPTH);
    }

    asm volatile("cp.async.wait_group 0;" ::: "memory");
    __syncthreads();

    // unpack lanes, butterfly-reduce, stash per-warp partials [8][32]
    float* s_part = s_buf;
    #pragma unroll
    for (int s = 0; s < 32; s++) {       // groups 0/1: slots 28-31 are zero
        const float lo = __uint_as_float((unsigned)(acc[s] & 0xffffffffu));
        const float hi = __uint_as_float((unsigned)(acc[s] >> 32));
        float vv = lo + hi;
        vv += __shfl_xor_sync(0xffffffffu, vv, 16);
        vv += __shfl_xor_sync(0xffffffffu, vv, 8);
        vv += __shfl_xor_sync(0xffffffffu, vv, 4);
        vv += __shfl_xor_sync(0xffffffffu, vv, 2);
        vv += __shfl_xor_sync(0xffffffffu, vv, 1);
        if (lane == 0) s_part[warp * 32 + s] = vv;
    }
    __syncthreads();

    // ---- fused finalize ----
    float* s_red = s_buf + 256;          // 4 floats
    float val = 0.0f;
    if (tid < 128) {
        const int fg   = tid >> 5;       // owning pair group
        const int slot = tid & 31;
        const int npk  = (fg < 2) ? 28 : 32;
        if (slot < npk) {
            const float S = s_part[(2 * fg) * 32 + slot] +
                            s_part[(2 * fg + 1) * 32 + slot];
            int c, d;
            if (fg < 2) {
                // triangular decode over 8 channels, c-major
                c = 0; int rem = slot;
                #pragma unroll
                for (int cc = 0; cc < 7; cc++) {
                    const int row = 7 - cc;
                    if (rem >= row && c == cc) { rem -= row; c = cc + 1; }
                }
                d = c + 1 + rem;
                if (fg == 1) { c += 8; d += 8; }
            } else {
                c = slot >> 2;
                d = ((fg == 2) ? 8 : 12) + (slot & 3);
            }
            val = g_wgt[g][c] * g_wgt[g][d] * fabsf(S);
        }
    }

    val += __shfl_xor_sync(0xffffffffu, val, 16);
    val += __shfl_xor_sync(0xffffffffu, val, 8);
    val += __shfl_xor_sync(0xffffffffu, val, 4);
    val += __shfl_xor_sync(0xffffffffu, val, 2);
    val += __shfl_xor_sync(0xffffffffu, val, 1);
    if (lane == 0 && warp < 4) s_red[warp] = val;
    __syncthreads();

    if (tid == 0) {
        const float tot = s_red[0] + s_red[1] + s_red[2] + s_red[3];
        const float sum_abs_cov = tot / (float)(HW - 1);
        const float off_diag    = sum_abs_cov - 60.0f;   // margin = floor(120/2)
        const float loss        = fmaxf(off_diag / 120.0f, 0.0f);
        atomicAdd(out, loss / (float)NB);
    }
}

// ---------------------------------------------------------------------------
extern "C" void kernel_launch(void* const* d_in, const int* in_sizes, int n_in,
                              void* d_out, int out_size) {
    (void)in_sizes; (void)n_in; (void)out_size;
    const float* x  = (const float*)d_in[0];   // [8,512,128,128] fp32
    const float* cw = (const float*)d_in[1];   // [19,512] fp32

    cudaFuncSetAttribute(gram_kernel,
                         cudaFuncAttributeMaxDynamicSharedMemorySize,
                         SMEM_BYTES);

    select_kernel<<<dim3(16, 8), 512>>>(cw, (float*)d_out);
    gram_kernel<<<NBG, 256, SMEM_BYTES>>>(x, (float*)d_out);
}

// round 16
// speedup vs baseline: 1.0788x; 1.0179x over previous
#include <cuda_runtime.h>
#include <math.h>

#define HW     16384
#define NCH    512
#define NC     16       // classes per group (C)
#define NG     32       // groups (G)
#define NB     8        // batch
#define NPAIR  120      // C*(C-1)/2
#define NBG    256      // NB*NG
#define TILE   256      // floats per channel per pipeline tile (1 KB)
#define NT     (HW / TILE)      // 64 tiles: one CTA covers the FULL HW
#define STAGES 6
#define DEPTH  5                // tiles in flight (80 KB per CTA)
#define STAGE_FLOATS (NC * TILE)                   // 4096 floats = 16 KB
#define SMEM_BYTES   (STAGES * STAGE_FLOATS * 4)   // 96 KB dynamic per CTA

typedef unsigned long long ull;

// Device-global scratch (no allocations allowed)
__device__ int   g_chan[NG][NC];        // channel id: rank-g pick of class c
__device__ float g_wgt[NG][NC];         // sigmoid(|w|) of that pick

// ---------------------------------------------------------------------------
// Kernel A: selection via rank counting (unchanged; measured 5.2-5.6us).
// Also zeroes out[0] (poisoned by harness; gram atomically accumulates).
// ---------------------------------------------------------------------------
__global__ void select_kernel(const float* __restrict__ cw,
                              float* __restrict__ out) {
    __shared__ float sw[NCH];
    const int j   = blockIdx.x;          // class
    const int q   = blockIdx.y;          // channel chunk (8 x 64)
    const int tid = threadIdx.x;

    if (j == 0 && q == 0 && tid == 0) out[0] = 0.0f;

    sw[tid] = fabsf(cw[j * NCH + tid]);
    __syncthreads();

    const int chl = tid >> 3;            // 0..63 channel-in-chunk
    const int sl  = tid & 7;             // compare slice
    const int i   = q * 64 + chl;        // global channel
    const float wi = sw[i];

    int r = 0;
    #pragma unroll 8
    for (int m = 0; m < 64; m++) {
        const int k = sl + (m << 3);     // interleaved: conflict-free
        const float wk = sw[k];
        r += (wk > wi) || (wk == wi && k < i);
    }
    r += __shfl_xor_sync(0xffffffffu, r, 1);
    r += __shfl_xor_sync(0xffffffffu, r, 2);
    r += __shfl_xor_sync(0xffffffffu, r, 4);

    if (sl == 0 && r < NG) {
        g_chan[r][j] = i;
        g_wgt[r][j]  = 1.0f / (1.0f + expf(-wi));
    }
}

// ---------------------------------------------------------------------------
// Kernel B: Gram + fused finalize, FFMA2 compute, LDS.128 tile reads.
// One CTA per (b,g), grid=256 (single wave), NT=64, 6-stage depth-5 cp.async.
// R16 change: issue(t+DEPTH) moved BEFORE the compute body — the next tile's
// DRAM burst is in flight while this tile computes (removes load/compute
// alternation; profile showed DRAM 45% + fma 29% with neither saturated).
// Safety: tile t+5 fills stage (t-1)%6, whose consumption the barrier at the
// top of round t just confirmed.
//   G0 (w0-1): 28 pairs within ch 0-7
//   G1 (w2-3): 28 pairs within ch 8-15
//   G2 (w4-5): 32 pairs c in 0-7, d in 8-11
//   G3 (w6-7): 32 pairs c in 0-7, d in 12-15
// ---------------------------------------------------------------------------
__device__ __forceinline__ void fma2(ull& a, ull b, ull c) {
    asm("fma.rn.f32x2 %0, %1, %2, %0;" : "+l"(a) : "l"(b), "l"(c));
}

template <int B>
__device__ __forceinline__ void body_oct(const ulonglong2* __restrict__ smu2,
                                         int lt, ull* __restrict__ acc) {
    ulonglong2 v[8];
    #pragma unroll
    for (int j = 0; j < 8; j++) v[j] = smu2[(B + j) * 64 + lt];
    int s = 0;
    #pragma unroll
    for (int c = 0; c < 8; c++)
        #pragma unroll
        for (int d = c + 1; d < 8; d++) {
            fma2(acc[s], v[c].x, v[d].x);
            fma2(acc[s], v[c].y, v[d].y);
            s++;
        }
}

template <int HB>
__device__ __forceinline__ void body_cross(const ulonglong2* __restrict__ smu2,
                                           int lt, ull* __restrict__ acc) {
    ulonglong2 vh[4];
    #pragma unroll
    for (int k = 0; k < 4; k++) vh[k] = smu2[(HB + k) * 64 + lt];
    #pragma unroll
    for (int c = 0; c < 8; c++) {
        const ulonglong2 vc = smu2[c * 64 + lt];
        #pragma unroll
        for (int k = 0; k < 4; k++) {
            fma2(acc[c * 4 + k], vc.x, vh[k].x);
            fma2(acc[c * 4 + k], vc.y, vh[k].y);
        }
    }
}

__global__ __launch_bounds__(256, 2) void gram_kernel(const float* __restrict__ x,
                                                      float* __restrict__ out) {
    extern __shared__ __align__(16) float s_buf[];   // [STAGES][NC][TILE]

    const int bg  = blockIdx.x;          // one CTA per (b,g)
    const int b   = bg >> 5;
    const int g   = bg & 31;
    const int tid = threadIdx.x;

    // loader role: 16 threads per channel
    const int mc = tid >> 4;             // channel 0..15
    const int ms = tid & 15;             // float4 slot within channel slice
    const float* src = x + ((size_t)(b * NCH + g_chan[g][mc])) * HW;

    // compute role
    const int grp  = tid >> 6;           // pair group 0..3 (2 warps each)
    const int lt   = tid & 63;           // ull2 position (covers ull 2lt,2lt+1)
    const int warp = tid >> 5;
    const int lane = tid & 31;

    auto issue = [&](int t) {
        const int stage = t % STAGES;
        const float4* gp = reinterpret_cast<const float4*>(src + t * TILE) + ms;
        float4* sp = reinterpret_cast<float4*>(
                         &s_buf[stage * STAGE_FLOATS + mc * TILE]) + ms;
        #pragma unroll
        for (int k = 0; k < 4; k++) {
            unsigned sa = (unsigned)__cvta_generic_to_shared(sp + 16 * k);
            asm volatile("cp.async.cg.shared.global [%0], [%1], 16;\n"
                         :: "r"(sa), "l"(gp + 16 * k) : "memory");
        }
        asm volatile("cp.async.commit_group;" ::: "memory");
    };

    ull acc[32];
    #pragma unroll
    for (int p = 0; p < 32; p++) acc[p] = 0ull;

    // prologue: DEPTH tiles in flight (one refill for the whole bg)
    #pragma unroll
    for (int t = 0; t < DEPTH; t++) issue(t);

    for (int t = 0; t < NT; t++) {
        asm volatile("cp.async.wait_group %0;" :: "n"(DEPTH - 1) : "memory");
        __syncthreads();                 // tile t visible; stage (t-1)%6 free

        // issue FIRST: next tile's DRAM burst overlaps this tile's compute
        if (t + DEPTH < NT) issue(t + DEPTH);

        const ulonglong2* smu2 = reinterpret_cast<const ulonglong2*>(
                                     &s_buf[(t % STAGES) * STAGE_FLOATS]);

        if      (grp == 0) body_oct<0>  (smu2, lt, acc);
        else if (grp == 1) body_oct<8>  (smu2, lt, acc);
        else if (grp == 2) body_cross<8> (smu2, lt, acc);
        else               body_cross<12>(smu2, lt, acc);
    }

    asm volatile("cp.async.wait_group 0;" ::: "memory");
    __syncthreads();

    // unpack lanes, butterfly-reduce, stash per-warp partials [8][32]
    float* s_part = s_buf;
    #pragma unroll
    for (int s = 0; s < 32; s++) {       // groups 0/1: slots 28-31 are zero
        const float lo = __uint_as_float((unsigned)(acc[s] & 0xffffffffu));
        const float hi = __uint_as_float((unsigned)(acc[s] >> 32));
        float vv = lo + hi;
        vv += __shfl_xor_sync(0xffffffffu, vv, 16);
        vv += __shfl_xor_sync(0xffffffffu, vv, 8);
        vv += __shfl_xor_sync(0xffffffffu, vv, 4);
        vv += __shfl_xor_sync(0xffffffffu, vv, 2);
        vv += __shfl_xor_sync(0xffffffffu, vv, 1);
        if (lane == 0) s_part[warp * 32 + s] = vv;
    }
    __syncthreads();

    // ---- fused finalize ----
    float* s_red = s_buf + 256;          // 4 floats
    float val = 0.0f;
    if (tid < 128) {
        const int fg   = tid >> 5;       // owning pair group
        const int slot = tid & 31;
        const int npk  = (fg < 2) ? 28 : 32;
        if (slot < npk) {
            const float S = s_part[(2 * fg) * 32 + slot] +
                            s_part[(2 * fg + 1) * 32 + slot];
            int c, d;
            if (fg < 2) {
                // triangular decode over 8 channels, c-major
                c = 0; int rem = slot;
                #pragma unroll
                for (int cc = 0; cc < 7; cc++) {
                    const int row = 7 - cc;
                    if (rem >= row && c == cc) { rem -= row; c = cc + 1; }
                }
                d = c + 1 + rem;
                if (fg == 1) { c += 8; d += 8; }
            } else {
                c = slot >> 2;
                d = ((fg == 2) ? 8 : 12) + (slot & 3);
            }
            val = g_wgt[g][c] * g_wgt[g][d] * fabsf(S);
        }
    }

    val += __shfl_xor_sync(0xffffffffu, val, 16);
    val += __shfl_xor_sync(0xffffffffu, val, 8);
    val += __shfl_xor_sync(0xffffffffu, val, 4);
    val += __shfl_xor_sync(0xffffffffu, val, 2);
    val += __shfl_xor_sync(0xffffffffu, val, 1);
    if (lane == 0 && warp < 4) s_red[warp] = val;
    __syncthreads();

    if (tid == 0) {
        const float tot = s_red[0] + s_red[1] + s_red[2] + s_red[3];
        const float sum_abs_cov = tot / (float)(HW - 1);
        const float off_diag    = sum_abs_cov - 60.0f;   // margin = floor(120/2)
        const float loss        = fmaxf(off_diag / 120.0f, 0.0f);
        atomicAdd(out, loss / (float)NB);
    }
}

// ---------------------------------------------------------------------------
extern "C" void kernel_launch(void* const* d_in, const int* in_sizes, int n_in,
                              void* d_out, int out_size) {
    (void)in_sizes; (void)n_in; (void)out_size;
    const float* x  = (const float*)d_in[0];   // [8,512,128,128] fp32
    const float* cw = (const float*)d_in[1];   // [19,512] fp32

    cudaFuncSetAttribute(gram_kernel,
                         cudaFuncAttributeMaxDynamicSharedMemorySize,
                         SMEM_BYTES);

    select_kernel<<<dim3(16, 8), 512>>>(cw, (float*)d_out);
    gram_kernel<<<NBG, 256, SMEM_BYTES>>>(x, (float*)d_out);
}

// round 17
// speedup vs baseline: 1.1711x; 1.0856x over previous
#include <cuda_runtime.h>
#include <math.h>

#define HW     16384
#define NCH    512
#define NC     16       // classes per group (C)
#define NG     32       // groups (G)
#define NB     8        // batch
#define NPAIR  120      // C*(C-1)/2
#define NBG    256      // NB*NG
#define TILE   512      // floats per channel per pipeline tile (2 KB)
#define NT     (HW / TILE)      // 32 tiles: one CTA covers the FULL HW
#define STAGES 3
#define DEPTH  2                // tiles in flight (64 KB per CTA)
#define STAGE_FLOATS (NC * TILE)                   // 8192 floats = 32 KB
#define SMEM_BYTES   (STAGES * STAGE_FLOATS * 4)   // 96 KB dynamic per CTA
#define U2CH   (TILE / 4)       // ull2 elements per channel row (128)

typedef unsigned long long ull;

// Device-global scratch (no allocations allowed)
__device__ int   g_chan[NG][NC];        // channel id: rank-g pick of class c
__device__ float g_wgt[NG][NC];         // sigmoid(|w|) of that pick

// ---------------------------------------------------------------------------
// Kernel A: selection via rank counting (unchanged; measured 5.2-5.6us).
// Also zeroes out[0] (poisoned by harness; gram atomically accumulates).
// ---------------------------------------------------------------------------
__global__ void select_kernel(const float* __restrict__ cw,
                              float* __restrict__ out) {
    __shared__ float sw[NCH];
    const int j   = blockIdx.x;          // class
    const int q   = blockIdx.y;          // channel chunk (8 x 64)
    const int tid = threadIdx.x;

    if (j == 0 && q == 0 && tid == 0) out[0] = 0.0f;

    sw[tid] = fabsf(cw[j * NCH + tid]);
    __syncthreads();

    const int chl = tid >> 3;            // 0..63 channel-in-chunk
    const int sl  = tid & 7;             // compare slice
    const int i   = q * 64 + chl;        // global channel
    const float wi = sw[i];

    int r = 0;
    #pragma unroll 8
    for (int m = 0; m < 64; m++) {
        const int k = sl + (m << 3);     // interleaved: conflict-free
        const float wk = sw[k];
        r += (wk > wi) || (wk == wi && k < i);
    }
    r += __shfl_xor_sync(0xffffffffu, r, 1);
    r += __shfl_xor_sync(0xffffffffu, r, 2);
    r += __shfl_xor_sync(0xffffffffu, r, 4);

    if (sl == 0 && r < NG) {
        g_chan[r][j] = i;
        g_wgt[r][j]  = 1.0f / (1.0f + expf(-wi));
    }
}

// ---------------------------------------------------------------------------
// Kernel B: Gram + fused finalize. TILE=512 / STAGES=3 / DEPTH=2:
// same 96 KB smem and same per-float smem traffic, but HALF the rounds
// (32 vs 64) -> the ~350 cyc/round fixed overhead (barrier convoy + wait +
// issue) is paid half as often. Compute body: FFMA2 + LDS.128, inner pp loop
// over the two ull2 positions per thread per tile.
//   G0 (w0-1): 28 pairs within ch 0-7
//   G1 (w2-3): 28 pairs within ch 8-15
//   G2 (w4-5): 32 pairs c in 0-7, d in 8-11
//   G3 (w6-7): 32 pairs c in 0-7, d in 12-15
// Issue-first retained: tile t+2 fills stage (t-1)%3, freed by round t-1.
// ---------------------------------------------------------------------------
__device__ __forceinline__ void fma2(ull& a, ull b, ull c) {
    asm("fma.rn.f32x2 %0, %1, %2, %0;" : "+l"(a) : "l"(b), "l"(c));
}

template <int B>
__device__ __forceinline__ void body_oct(const ulonglong2* __restrict__ smu2,
                                         int lt, ull* __restrict__ acc) {
    #pragma unroll
    for (int pp = 0; pp < 2; pp++) {
        const int pos = lt + pp * 64;
        ulonglong2 v[8];
        #pragma unroll
        for (int j = 0; j < 8; j++) v[j] = smu2[(B + j) * U2CH + pos];
        int s = 0;
        #pragma unroll
        for (int c = 0; c < 8; c++)
            #pragma unroll
            for (int d = c + 1; d < 8; d++) {
                fma2(acc[s], v[c].x, v[d].x);
                fma2(acc[s], v[c].y, v[d].y);
                s++;
            }
    }
}

template <int HB>
__device__ __forceinline__ void body_cross(const ulonglong2* __restrict__ smu2,
                                           int lt, ull* __restrict__ acc) {
    #pragma unroll
    for (int pp = 0; pp < 2; pp++) {
        const int pos = lt + pp * 64;
        ulonglong2 vh[4];
        #pragma unroll
        for (int k = 0; k < 4; k++) vh[k] = smu2[(HB + k) * U2CH + pos];
        #pragma unroll
        for (int c = 0; c < 8; c++) {
            const ulonglong2 vc = smu2[c * U2CH + pos];
            #pragma unroll
            for (int k = 0; k < 4; k++) {
                fma2(acc[c * 4 + k], vc.x, vh[k].x);
                fma2(acc[c * 4 + k], vc.y, vh[k].y);
            }
        }
    }
}

__global__ __launch_bounds__(256, 2) void gram_kernel(const float* __restrict__ x,
                                                      float* __restrict__ out) {
    extern __shared__ __align__(16) float s_buf[];   // [STAGES][NC][TILE]

    const int bg  = blockIdx.x;          // one CTA per (b,g)
    const int b   = bg >> 5;
    const int g   = bg & 31;
    const int tid = threadIdx.x;

    // loader role: 16 threads per channel, 8 float4 (128 B) each per tile
    const int mc = tid >> 4;             // channel 0..15
    const int ms = tid & 15;             // float4 slot within channel slice
    const float* src = x + ((size_t)(b * NCH + g_chan[g][mc])) * HW;

    // compute role
    const int grp  = tid >> 6;           // pair group 0..3 (2 warps each)
    const int lt   = tid & 63;           // base ull2 position (covers lt, lt+64)
    const int warp = tid >> 5;
    const int lane = tid & 31;

    auto issue = [&](int t) {
        const int stage = t % STAGES;
        const float4* gp = reinterpret_cast<const float4*>(src + t * TILE) + ms;
        float4* sp = reinterpret_cast<float4*>(
                         &s_buf[stage * STAGE_FLOATS + mc * TILE]) + ms;
        #pragma unroll
        for (int k = 0; k < 8; k++) {
            unsigned sa = (unsigned)__cvta_generic_to_shared(sp + 16 * k);
            asm volatile("cp.async.cg.shared.global [%0], [%1], 16;\n"
                         :: "r"(sa), "l"(gp + 16 * k) : "memory");
        }
        asm volatile("cp.async.commit_group;" ::: "memory");
    };

    ull acc[32];
    #pragma unroll
    for (int p = 0; p < 32; p++) acc[p] = 0ull;

    // prologue: DEPTH tiles in flight
    #pragma unroll
    for (int t = 0; t < DEPTH; t++) issue(t);

    for (int t = 0; t < NT; t++) {
        asm volatile("cp.async.wait_group %0;" :: "n"(DEPTH - 1) : "memory");
        __syncthreads();                 // tile t visible; stage (t-1)%3 free

        // issue FIRST: next tile's DRAM burst overlaps this tile's compute
        if (t + DEPTH < NT) issue(t + DEPTH);

        const ulonglong2* smu2 = reinterpret_cast<const ulonglong2*>(
                                     &s_buf[(t % STAGES) * STAGE_FLOATS]);

        if      (grp == 0) body_oct<0>  (smu2, lt, acc);
        else if (grp == 1) body_oct<8>  (smu2, lt, acc);
        else if (grp == 2) body_cross<8> (smu2, lt, acc);
        else               body_cross<12>(smu2, lt, acc);
    }

    asm volatile("cp.async.wait_group 0;" ::: "memory");
    __syncthreads();

    // unpack lanes, butterfly-reduce, stash per-warp partials [8][32]
    float* s_part = s_buf;
    #pragma unroll
    for (int s = 0; s < 32; s++) {       // groups 0/1: slots 28-31 are zero
        const float lo = __uint_as_float((unsigned)(acc[s] & 0xffffffffu));
        const float hi = __uint_as_float((unsigned)(acc[s] >> 32));
        float vv = lo + hi;
        vv += __shfl_xor_sync(0xffffffffu, vv, 16);
        vv += __shfl_xor_sync(0xffffffffu, vv, 8);
        vv += __shfl_xor_sync(0xffffffffu, vv, 4);
        vv += __shfl_xor_sync(0xffffffffu, vv, 2);
        vv += __shfl_xor_sync(0xffffffffu, vv, 1);
        if (lane == 0) s_part[warp * 32 + s] = vv;
    }
    __syncthreads();

    // ---- fused finalize ----
    float* s_red = s_buf + 256;          // 4 floats
    float val = 0.0f;
    if (tid < 128) {
        const int fg   = tid >> 5;       // owning pair group
        const int slot = tid & 31;
        const int npk  = (fg < 2) ? 28 : 32;
        if (slot < npk) {
            const float S = s_part[(2 * fg) * 32 + slot] +
                            s_part[(2 * fg + 1) * 32 + slot];
            int c, d;
            if (fg < 2) {
                // triangular decode over 8 channels, c-major
                c = 0; int rem = slot;
                #pragma unroll
                for (int cc = 0; cc < 7; cc++) {
                    const int row = 7 - cc;
                    if (rem >= row && c == cc) { rem -= row; c = cc + 1; }
                }
                d = c + 1 + rem;
                if (fg == 1) { c += 8; d += 8; }
            } else {
                c = slot >> 2;
                d = ((fg == 2) ? 8 : 12) + (slot & 3);
            }
            val = g_wgt[g][c] * g_wgt[g][d] * fabsf(S);
        }
    }

    val += __shfl_xor_sync(0xffffffffu, val, 16);
    val += __shfl_xor_sync(0xffffffffu, val, 8);
    val += __shfl_xor_sync(0xffffffffu, val, 4);
    val += __shfl_xor_sync(0xffffffffu, val, 2);
    val += __shfl_xor_sync(0xffffffffu, val, 1);
    if (lane == 0 && warp < 4) s_red[warp] = val;
    __syncthreads();

    if (tid == 0) {
        const float tot = s_red[0] + s_red[1] + s_red[2] + s_red[3];
        const float sum_abs_cov = tot / (float)(HW - 1);
        const float off_diag    = sum_abs_cov - 60.0f;   // margin = floor(120/2)
        const float loss        = fmaxf(off_diag / 120.0f, 0.0f);
        atomicAdd(out, loss / (float)NB);
    }
}

// ---------------------------------------------------------------------------
extern "C" void kernel_launch(void* const* d_in, const int* in_sizes, int n_in,
                              void* d_out, int out_size) {
    (void)in_sizes; (void)n_in; (void)out_size;
    const float* x  = (const float*)d_in[0];   // [8,512,128,128] fp32
    const float* cw = (const float*)d_in[1];   // [19,512] fp32

    cudaFuncSetAttribute(gram_kernel,
                         cudaFuncAttributeMaxDynamicSharedMemorySize,
                         SMEM_BYTES);

    select_kernel<<<dim3(16, 8), 512>>>(cw, (float*)d_out);
    gram_kernel<<<NBG, 256, SMEM_BYTES>>>(x, (float*)d_out);
}